// round 1
// baseline (speedup 1.0000x reference)
#include <cuda_runtime.h>

// DySepConvAtten fused kernel: per-batch CTA.
// B=512, N=100 (padded 104), C=256, K=3, J=N+K=103 (padded 104 / dy rows padded to 128 cols)
#define NROW 100
#define NPAD 104
#define CDIM 256
#define JDIM 103
#define JP   104
#define RPW  13            // rows per warp (8 warps x 13 = 104 padded rows)
#define REG1 26624         // floats: W [256][104]  -> depth [104][256]
#define REG2 26624         // floats: Q [104][256]  -> dy    [104][128]
#define SMEM_FLOATS (REG1 + REG2 + 104)

__global__ void __launch_bounds__(256, 1)
dysep_kernel(const float* __restrict__ query, const float* __restrict__ value,
             const float* __restrict__ Wwl,   const float* __restrict__ bwl,
             const float* __restrict__ gamma, const float* __restrict__ beta,
             float* __restrict__ out)
{
    extern __shared__ float sm[];
    float* s1 = sm;             // phase A: W[c][j] (stride JP); phase B/C: depth[m][c] (stride 256)
    float* s2 = sm + REG1;      // phase A: Q[n][c] (stride 256); later: dy[n][j] (stride 128)
    float* sB = sm + REG1 + REG2;  // bias [104]

    const int b    = blockIdx.x;
    const int tid  = threadIdx.x;
    const int w    = tid >> 5;
    const int lane = tid & 31;

    const float* qg = query + (size_t)b * (NROW * CDIM);
    const float* vg = value + (size_t)b * (NROW * CDIM);
    float*       og = out   + (size_t)b * (NROW * CDIM);

    // ---- stage W into s1 (pad col 103 = garbage-safe, but zero it), Q into s2 ----
    for (int idx = tid; idx < CDIM * JDIM; idx += 256) {
        int c = idx / JDIM;
        int j = idx - c * JDIM;
        s1[c * JP + j] = Wwl[idx];
    }
    if (tid < CDIM) s1[tid * JP + JDIM] = 0.0f;      // zero the pad column
    for (int idx = tid; idx < NROW * CDIM; idx += 256)
        s2[idx] = qg[idx];
    for (int idx = tid; idx < 4 * CDIM; idx += 256)   // zero pad rows 100..103 of Q
        s2[NROW * CDIM + idx] = 0.0f;
    if (tid < JP) sB[tid] = (tid < JDIM) ? bwl[tid] : 0.0f;
    __syncthreads();

    // ================= Phase A: dy = Q @ W + b =================
    // lane covers j = 4*lane .. 4*lane+3 (lanes 26..31 clamped duplicates, results unused)
    const int jb = (lane < 26) ? (lane * 4) : 100;
    float acc[RPW][4];
    {
        float4 bv = *(const float4*)(sB + jb);
        #pragma unroll
        for (int r = 0; r < RPW; ++r) {
            acc[r][0] = bv.x; acc[r][1] = bv.y; acc[r][2] = bv.z; acc[r][3] = bv.w;
        }
    }
    #pragma unroll 1
    for (int c0 = 0; c0 < CDIM; c0 += 4) {
        const float4 w0 = *(const float4*)(s1 + (c0 + 0) * JP + jb);
        const float4 w1 = *(const float4*)(s1 + (c0 + 1) * JP + jb);
        const float4 w2 = *(const float4*)(s1 + (c0 + 2) * JP + jb);
        const float4 w3 = *(const float4*)(s1 + (c0 + 3) * JP + jb);
        #pragma unroll
        for (int r = 0; r < RPW; ++r) {
            const float4 qv = *(const float4*)(s2 + (w + 8 * r) * CDIM + c0);
            acc[r][0] = fmaf(qv.x, w0.x, acc[r][0]);
            acc[r][1] = fmaf(qv.x, w0.y, acc[r][1]);
            acc[r][2] = fmaf(qv.x, w0.z, acc[r][2]);
            acc[r][3] = fmaf(qv.x, w0.w, acc[r][3]);
            acc[r][0] = fmaf(qv.y, w1.x, acc[r][0]);
            acc[r][1] = fmaf(qv.y, w1.y, acc[r][1]);
            acc[r][2] = fmaf(qv.y, w1.z, acc[r][2]);
            acc[r][3] = fmaf(qv.y, w1.w, acc[r][3]);
            acc[r][0] = fmaf(qv.z, w2.x, acc[r][0]);
            acc[r][1] = fmaf(qv.z, w2.y, acc[r][1]);
            acc[r][2] = fmaf(qv.z, w2.z, acc[r][2]);
            acc[r][3] = fmaf(qv.z, w2.w, acc[r][3]);
            acc[r][0] = fmaf(qv.w, w3.x, acc[r][0]);
            acc[r][1] = fmaf(qv.w, w3.y, acc[r][1]);
            acc[r][2] = fmaf(qv.w, w3.z, acc[r][2]);
            acc[r][3] = fmaf(qv.w, w3.w, acc[r][3]);
        }
    }
    __syncthreads();   // all Q reads done; s2 becomes dy storage

    #pragma unroll
    for (int r = 0; r < RPW; ++r) {
        float4 v4 = make_float4(acc[r][0], acc[r][1], acc[r][2], acc[r][3]);
        *(float4*)(s2 + (w + 8 * r) * 128 + lane * 4) = v4;   // dy row stride 128
    }
    __syncthreads();

    // ================= Phase B: depth = relu(depthwise conv over C) into s1 =================
    // depth[m][c] = dw0*v[c-1] + dw1*v[c] + dw2*v[c+1]  (zero pad)
    for (int idx = tid; idx < NPAD * (CDIM / 4); idx += 256) {
        int m = idx >> 6;
        int c = (idx & 63) * 4;
        int mg = (m < NROW) ? m : (NROW - 1);
        const float* vr = vg + mg * CDIM;
        float d0 = s2[m * 128 + 0];
        float d1 = s2[m * 128 + 1];
        float d2 = s2[m * 128 + 2];
        float4 vc = *(const float4*)(vr + c);
        float vl = (c == 0)        ? 0.0f : vr[c - 1];
        float vr2 = (c == CDIM - 4) ? 0.0f : vr[c + 4];
        float4 o;
        o.x = fmaxf(fmaf(d0, vl,   fmaf(d1, vc.x, d2 * vc.y)), 0.0f);
        o.y = fmaxf(fmaf(d0, vc.x, fmaf(d1, vc.y, d2 * vc.z)), 0.0f);
        o.z = fmaxf(fmaf(d0, vc.y, fmaf(d1, vc.z, d2 * vc.w)), 0.0f);
        o.w = fmaxf(fmaf(d0, vc.z, fmaf(d1, vc.w, d2 * vr2)), 0.0f);
        *(float4*)(s1 + m * CDIM + c) = o;
    }
    __syncthreads();

    // ================= Phase C: out = pw @ depth =================
    // pw[n][m] = dy[n][3+m]; lane covers c = 8*lane .. 8*lane+7
    float a2[RPW][8];
    #pragma unroll
    for (int r = 0; r < RPW; ++r)
        #pragma unroll
        for (int t = 0; t < 8; ++t) a2[r][t] = 0.0f;

    const int cb = lane * 8;
    #pragma unroll 2
    for (int m = 0; m < NROW; ++m) {
        const float4 e0 = *(const float4*)(s1 + m * CDIM + cb);
        const float4 e1 = *(const float4*)(s1 + m * CDIM + cb + 4);
        #pragma unroll
        for (int r = 0; r < RPW; ++r) {
            const float p = s2[(w + 8 * r) * 128 + 3 + m];
            a2[r][0] = fmaf(p, e0.x, a2[r][0]);
            a2[r][1] = fmaf(p, e0.y, a2[r][1]);
            a2[r][2] = fmaf(p, e0.z, a2[r][2]);
            a2[r][3] = fmaf(p, e0.w, a2[r][3]);
            a2[r][4] = fmaf(p, e1.x, a2[r][4]);
            a2[r][5] = fmaf(p, e1.y, a2[r][5]);
            a2[r][6] = fmaf(p, e1.z, a2[r][6]);
            a2[r][7] = fmaf(p, e1.w, a2[r][7]);
        }
    }

    // ================= Phase D: LayerNorm over C + store =================
    const float rC = 1.0f / (float)CDIM;
    const float4 g0 = *(const float4*)(gamma + cb);
    const float4 g1 = *(const float4*)(gamma + cb + 4);
    const float4 t0 = *(const float4*)(beta + cb);
    const float4 t1 = *(const float4*)(beta + cb + 4);
    #pragma unroll
    for (int r = 0; r < RPW; ++r) {
        const int n = w + 8 * r;
        if (n >= NROW) break;     // uniform across warp
        float s = 0.0f, ss = 0.0f;
        #pragma unroll
        for (int t = 0; t < 8; ++t) {
            s += a2[r][t];
            ss = fmaf(a2[r][t], a2[r][t], ss);
        }
        #pragma unroll
        for (int o = 16; o > 0; o >>= 1) {
            s  += __shfl_xor_sync(0xffffffffu, s, o);
            ss += __shfl_xor_sync(0xffffffffu, ss, o);
        }
        const float mu  = s * rC;
        float var = fmaf(-mu, mu, ss * rC);
        var = fmaxf(var, 0.0f);
        const float inv = rsqrtf(var + 1e-5f);
        float4 o0, o1;
        o0.x = fmaf((a2[r][0] - mu) * inv, g0.x, t0.x);
        o0.y = fmaf((a2[r][1] - mu) * inv, g0.y, t0.y);
        o0.z = fmaf((a2[r][2] - mu) * inv, g0.z, t0.z);
        o0.w = fmaf((a2[r][3] - mu) * inv, g0.w, t0.w);
        o1.x = fmaf((a2[r][4] - mu) * inv, g1.x, t1.x);
        o1.y = fmaf((a2[r][5] - mu) * inv, g1.y, t1.y);
        o1.z = fmaf((a2[r][6] - mu) * inv, g1.z, t1.z);
        o1.w = fmaf((a2[r][7] - mu) * inv, g1.w, t1.w);
        *(float4*)(og + n * CDIM + cb)     = o0;
        *(float4*)(og + n * CDIM + cb + 4) = o1;
    }
}

extern "C" void kernel_launch(void* const* d_in, const int* in_sizes, int n_in,
                              void* d_out, int out_size)
{
    const float* query = (const float*)d_in[0];
    const float* value = (const float*)d_in[1];
    const float* Wwl   = (const float*)d_in[2];
    const float* bwl   = (const float*)d_in[3];
    const float* gamma = (const float*)d_in[4];
    const float* beta  = (const float*)d_in[5];
    float* out = (float*)d_out;

    const int B = in_sizes[0] / (NROW * CDIM);   // 512
    const size_t smem = SMEM_FLOATS * sizeof(float);   // 213,408 B
    cudaFuncSetAttribute(dysep_kernel,
                         cudaFuncAttributeMaxDynamicSharedMemorySize, (int)smem);
    dysep_kernel<<<B, 256, smem>>>(query, value, Wwl, bwl, gamma, beta, out);
}

// round 2
// speedup vs baseline: 1.1704x; 1.1704x over previous
#include <cuda_runtime.h>

// DySepConvAtten fused kernel v2: per-batch CTA, 512 threads, f32x2 FMA.
// B=512, N=100, C=256, K=3, J=N+K=103 (pad 104). Row slots padded to 112 (16 warps x 7).
#define NROW 100
#define NPAD 112
#define CDIM 256
#define JDIM 103
#define JP   104
#define NTHR 512
#define NWARP 16
#define RPW  7             // rows per warp (16 warps x 7 = 112 row slots)
#define REG1 26624         // floats: W [256][104] -> depth [100][256] (25600)
#define REG2 25600         // floats: Q [100][256] -> dy [112][128] (14336)
#define SMEM_FLOATS (REG1 + REG2 + 112)

typedef unsigned long long u64;

__device__ __forceinline__ u64 pack2(float lo, float hi) {
    u64 r;
    asm("mov.b64 %0, {%1, %2};" : "=l"(r) : "f"(lo), "f"(hi));
    return r;
}
__device__ __forceinline__ void fma2(u64 &d, u64 a, u64 b) {
    asm("fma.rn.f32x2 %0, %1, %2, %0;" : "+l"(d) : "l"(a), "l"(b));
}
__device__ __forceinline__ float2 unpack2(u64 v) {
    float2 f;
    asm("mov.b64 {%0, %1}, %2;" : "=f"(f.x), "=f"(f.y) : "l"(v));
    return f;
}

__global__ void __launch_bounds__(NTHR, 1)
dysep_kernel(const float* __restrict__ query, const float* __restrict__ value,
             const float* __restrict__ Wwl,   const float* __restrict__ bwl,
             const float* __restrict__ gamma, const float* __restrict__ beta,
             float* __restrict__ out)
{
    extern __shared__ float sm[];
    float* s1 = sm;                 // phase A: W[c][j] stride JP; phase B/C: depth[m][c] stride 256
    float* s2 = sm + REG1;          // phase A: Q[n][c] stride 256 (100 rows); later: dy[n][j] stride 128 (112 rows)
    float* sB = sm + REG1 + REG2;   // bias [112]

    const int b    = blockIdx.x;
    const int tid  = threadIdx.x;
    const int w    = tid >> 5;
    const int lane = tid & 31;

    const float* qg = query + (size_t)b * (NROW * CDIM);
    const float* vg = value + (size_t)b * (NROW * CDIM);
    float*       og = out   + (size_t)b * (NROW * CDIM);

    // ---- stage W (stride JP, pad col 103 zeroed), Q (100 rows), bias ----
    for (int idx = tid; idx < CDIM * JDIM; idx += NTHR) {
        int c = idx / JDIM;
        int j = idx - c * JDIM;
        s1[c * JP + j] = Wwl[idx];
    }
    if (tid < CDIM) s1[tid * JP + JDIM] = 0.0f;
    for (int idx = tid; idx < NROW * CDIM; idx += NTHR)
        s2[idx] = qg[idx];
    if (tid < NPAD) sB[tid] = (tid < JDIM) ? bwl[tid] : 0.0f;
    __syncthreads();

    // ================= Phase A: dy = Q @ W + b  (f32x2) =================
    // lane covers j = 4*lane .. 4*lane+3 (lanes 26..31 duplicate jb=100, harmless)
    const int jb = (lane < 26) ? (lane * 4) : 100;
    u64 acc[RPW][2];
    {
        const ulonglong2 bv = *(const ulonglong2*)(sB + jb);
        #pragma unroll
        for (int r = 0; r < RPW; ++r) { acc[r][0] = bv.x; acc[r][1] = bv.y; }
    }
    #pragma unroll 1
    for (int c0 = 0; c0 < CDIM; c0 += 4) {
        const ulonglong2 w0 = *(const ulonglong2*)(s1 + (c0 + 0) * JP + jb);
        const ulonglong2 w1 = *(const ulonglong2*)(s1 + (c0 + 1) * JP + jb);
        const ulonglong2 w2 = *(const ulonglong2*)(s1 + (c0 + 2) * JP + jb);
        const ulonglong2 w3 = *(const ulonglong2*)(s1 + (c0 + 3) * JP + jb);
        #pragma unroll
        for (int r = 0; r < RPW; ++r) {
            const int n = w + NWARP * r;
            const int ne = (n < NROW) ? n : (NROW - 1);   // clamp pad rows (uniform per warp)
            const float4 qv = *(const float4*)(s2 + ne * CDIM + c0);
            const u64 qx = pack2(qv.x, qv.x);
            const u64 qy = pack2(qv.y, qv.y);
            const u64 qz = pack2(qv.z, qv.z);
            const u64 qw = pack2(qv.w, qv.w);
            fma2(acc[r][0], qx, w0.x); fma2(acc[r][1], qx, w0.y);
            fma2(acc[r][0], qy, w1.x); fma2(acc[r][1], qy, w1.y);
            fma2(acc[r][0], qz, w2.x); fma2(acc[r][1], qz, w2.y);
            fma2(acc[r][0], qw, w3.x); fma2(acc[r][1], qw, w3.y);
        }
    }
    __syncthreads();   // all Q reads done; s2 becomes dy storage

    #pragma unroll
    for (int r = 0; r < RPW; ++r) {
        const int n = w + NWARP * r;
        *(ulonglong2*)(s2 + n * 128 + lane * 4) = make_ulonglong2(acc[r][0], acc[r][1]);
    }
    __syncthreads();

    // ================= Phase B: depth = relu(depthwise conv over C) into s1 =================
    for (int idx = tid; idx < NROW * (CDIM / 4); idx += NTHR) {
        const int m = idx >> 6;
        const int c = (idx & 63) * 4;
        const float* vr = vg + m * CDIM;
        const float d0 = s2[m * 128 + 0];
        const float d1 = s2[m * 128 + 1];
        const float d2 = s2[m * 128 + 2];
        const float4 vc = *(const float4*)(vr + c);
        const float vl  = (c == 0)        ? 0.0f : vr[c - 1];
        const float vrt = (c == CDIM - 4) ? 0.0f : vr[c + 4];
        float4 o;
        o.x = fmaxf(fmaf(d0, vl,   fmaf(d1, vc.x, d2 * vc.y)), 0.0f);
        o.y = fmaxf(fmaf(d0, vc.x, fmaf(d1, vc.y, d2 * vc.z)), 0.0f);
        o.z = fmaxf(fmaf(d0, vc.y, fmaf(d1, vc.z, d2 * vc.w)), 0.0f);
        o.w = fmaxf(fmaf(d0, vc.z, fmaf(d1, vc.w, d2 * vrt)), 0.0f);
        *(float4*)(s1 + m * CDIM + c) = o;
    }
    __syncthreads();

    // ================= Phase C: out = pw @ depth  (f32x2) =================
    // pw[n][m] = dy[n][3+m]; lane covers c = 8*lane .. 8*lane+7 as 4 c-pairs
    u64 a2[RPW][4];
    #pragma unroll
    for (int r = 0; r < RPW; ++r)
        #pragma unroll
        for (int t = 0; t < 4; ++t) a2[r][t] = 0ull;

    const int cb = lane * 8;
    #pragma unroll 1
    for (int m0 = 0; m0 < NROW; m0 += 4) {
        #pragma unroll
        for (int mi = 0; mi < 4; ++mi) {
            const int m = m0 + mi;
            const ulonglong2 e0 = *(const ulonglong2*)(s1 + m * CDIM + cb);
            const ulonglong2 e1 = *(const ulonglong2*)(s1 + m * CDIM + cb + 4);
            #pragma unroll
            for (int r = 0; r < RPW; ++r) {
                const int n = w + NWARP * r;
                const float ps = s2[n * 128 + 3 + m];
                const u64 p2 = pack2(ps, ps);
                fma2(a2[r][0], p2, e0.x);
                fma2(a2[r][1], p2, e0.y);
                fma2(a2[r][2], p2, e1.x);
                fma2(a2[r][3], p2, e1.y);
            }
        }
    }

    // ================= Phase D: LayerNorm over C + store =================
    const float rC = 1.0f / (float)CDIM;
    #pragma unroll
    for (int r = 0; r < RPW; ++r) {
        const int n = w + NWARP * r;
        if (n >= NROW) break;     // uniform across warp
        float2 v[4];
        #pragma unroll
        for (int t = 0; t < 4; ++t) v[t] = unpack2(a2[r][t]);
        float s = 0.0f, ss = 0.0f;
        #pragma unroll
        for (int t = 0; t < 4; ++t) {
            s += v[t].x + v[t].y;
            ss = fmaf(v[t].x, v[t].x, ss);
            ss = fmaf(v[t].y, v[t].y, ss);
        }
        #pragma unroll
        for (int o = 16; o > 0; o >>= 1) {
            s  += __shfl_xor_sync(0xffffffffu, s, o);
            ss += __shfl_xor_sync(0xffffffffu, ss, o);
        }
        const float mu  = s * rC;
        float var = fmaf(-mu, mu, ss * rC);
        var = fmaxf(var, 0.0f);
        const float inv = rsqrtf(var + 1e-5f);
        const float4 g0 = *(const float4*)(gamma + cb);
        const float4 g1 = *(const float4*)(gamma + cb + 4);
        const float4 t0 = *(const float4*)(beta + cb);
        const float4 t1 = *(const float4*)(beta + cb + 4);
        float4 o0, o1;
        o0.x = fmaf((v[0].x - mu) * inv, g0.x, t0.x);
        o0.y = fmaf((v[0].y - mu) * inv, g0.y, t0.y);
        o0.z = fmaf((v[1].x - mu) * inv, g0.z, t0.z);
        o0.w = fmaf((v[1].y - mu) * inv, g0.w, t0.w);
        o1.x = fmaf((v[2].x - mu) * inv, g1.x, t1.x);
        o1.y = fmaf((v[2].y - mu) * inv, g1.y, t1.y);
        o1.z = fmaf((v[3].x - mu) * inv, g1.z, t1.z);
        o1.w = fmaf((v[3].y - mu) * inv, g1.w, t1.w);
        *(float4*)(og + n * CDIM + cb)     = o0;
        *(float4*)(og + n * CDIM + cb + 4) = o1;
    }
}

extern "C" void kernel_launch(void* const* d_in, const int* in_sizes, int n_in,
                              void* d_out, int out_size)
{
    const float* query = (const float*)d_in[0];
    const float* value = (const float*)d_in[1];
    const float* Wwl   = (const float*)d_in[2];
    const float* bwl   = (const float*)d_in[3];
    const float* gamma = (const float*)d_in[4];
    const float* beta  = (const float*)d_in[5];
    float* out = (float*)d_out;

    const int B = in_sizes[0] / (NROW * CDIM);   // 512
    const size_t smem = SMEM_FLOATS * sizeof(float);   // 209,344 B
    cudaFuncSetAttribute(dysep_kernel,
                         cudaFuncAttributeMaxDynamicSharedMemorySize, (int)smem);
    dysep_kernel<<<B, NTHR, smem>>>(query, value, Wwl, bwl, gamma, beta, out);
}

// round 4
// speedup vs baseline: 1.2824x; 1.0957x over previous
#include <cuda_runtime.h>

// DySepConvAtten fused kernel v3: per-batch CTA, 512 threads, f32x2 FMA,
// conflict-free phase-C layout, aligned pre-shifted pw, dead-row guards.
#define NROW 100
#define CDIM 256
#define JDIM 103
#define JP   104
#define NTHR 512
#define NWARP 16
#define RPW  7              // row slots per warp (16 x 7 = 112)
#define REG1 26624          // floats: W [256][104] -> depth [100][256]
#define REG2 25600          // floats: Q [100][256] -> pwS [112][104] + dw [112][4]
#define PWROWS 11648        // 112*104
#define SMEM_FLOATS (REG1 + REG2 + 112)

typedef unsigned long long u64;

__device__ __forceinline__ u64 pack2(float lo, float hi) {
    u64 r;
    asm("mov.b64 %0, {%1, %2};" : "=l"(r) : "f"(lo), "f"(hi));
    return r;
}
__device__ __forceinline__ void fma2(u64 &d, u64 a, u64 b) {
    asm("fma.rn.f32x2 %0, %1, %2, %0;" : "+l"(d) : "l"(a), "l"(b));
}
__device__ __forceinline__ float2 unpack2(u64 v) {
    float2 f;
    asm("mov.b64 {%0, %1}, %2;" : "=f"(f.x), "=f"(f.y) : "l"(v));
    return f;
}

__global__ void __launch_bounds__(NTHR, 1)
dysep_kernel(const float* __restrict__ query, const float* __restrict__ value,
             const float* __restrict__ Wwl,   const float* __restrict__ bwl,
             const float* __restrict__ gamma, const float* __restrict__ beta,
             float* __restrict__ out)
{
    extern __shared__ float sm[];
    float* s1  = sm;                  // phase A: W[c][j] stride JP; phase B/C: depth[m][c] stride 256
    float* s2  = sm + REG1;           // phase A: Q[n][c] stride 256; later pwS/dw
    float* pwS = sm + REG1;           // [112][104]: pw[n][m] = dy[n][3+m]
    float* dwS = sm + REG1 + PWROWS;  // [112][4]:   dw[n][k] = dy[n][k], k<3
    float* sB  = sm + REG1 + REG2;    // bias [112]

    const int b    = blockIdx.x;
    const int tid  = threadIdx.x;
    const int w    = tid >> 5;
    const int lane = tid & 31;

    const float* qg = query + (size_t)b * (NROW * CDIM);
    const float* vg = value + (size_t)b * (NROW * CDIM);
    float*       og = out   + (size_t)b * (NROW * CDIM);

    // ---- stage W (stride JP, pad col 103 zeroed), Q, bias ----
    for (int idx = tid; idx < CDIM * JDIM; idx += NTHR) {
        int c = idx / JDIM;
        int j = idx - c * JDIM;
        s1[c * JP + j] = Wwl[idx];
    }
    if (tid < CDIM) s1[tid * JP + JDIM] = 0.0f;
    for (int idx = tid; idx < NROW * CDIM; idx += NTHR)
        s2[idx] = qg[idx];
    if (tid < 112) sB[tid] = (tid < JDIM) ? bwl[tid] : 0.0f;
    __syncthreads();

    // ================= Phase A: dy = Q @ W + b  (f32x2, j packed) =================
    // lane covers j = 4*lane .. 4*lane+3 (lanes >= 26 duplicate jb=100)
    const int jb = (lane < 26) ? (lane * 4) : 100;
    u64 acc[RPW][2];
    {
        const ulonglong2 bv = *(const ulonglong2*)(sB + jb);
        #pragma unroll
        for (int r = 0; r < RPW; ++r) { acc[r][0] = bv.x; acc[r][1] = bv.y; }
    }
    #pragma unroll 2
    for (int c0 = 0; c0 < CDIM; c0 += 4) {
        const ulonglong2 w0 = *(const ulonglong2*)(s1 + (c0 + 0) * JP + jb);
        const ulonglong2 w1 = *(const ulonglong2*)(s1 + (c0 + 1) * JP + jb);
        const ulonglong2 w2 = *(const ulonglong2*)(s1 + (c0 + 2) * JP + jb);
        const ulonglong2 w3 = *(const ulonglong2*)(s1 + (c0 + 3) * JP + jb);
        #pragma unroll
        for (int r = 0; r < RPW; ++r) {
            const int n = w + NWARP * r;
            if (n < NROW) {                       // warp-uniform guard
                const float4 qv = *(const float4*)(s2 + n * CDIM + c0);
                const u64 qx = pack2(qv.x, qv.x);
                const u64 qy = pack2(qv.y, qv.y);
                const u64 qz = pack2(qv.z, qv.z);
                const u64 qw = pack2(qv.w, qv.w);
                fma2(acc[r][0], qx, w0.x); fma2(acc[r][1], qx, w0.y);
                fma2(acc[r][0], qy, w1.x); fma2(acc[r][1], qy, w1.y);
                fma2(acc[r][0], qz, w2.x); fma2(acc[r][1], qz, w2.y);
                fma2(acc[r][0], qw, w3.x); fma2(acc[r][1], qw, w3.y);
            }
        }
    }
    __syncthreads();   // all Q reads done; s2 becomes pwS/dw storage

    // ---- writeback: split dy into shifted-aligned pw and tiny dw ----
    #pragma unroll
    for (int r = 0; r < RPW; ++r) {
        const int n = w + NWARP * r;
        if (n < NROW) {
            const float2 v0 = unpack2(acc[r][0]);
            const float2 v1 = unpack2(acc[r][1]);
            float vj[4] = {v0.x, v0.y, v1.x, v1.y};
            #pragma unroll
            for (int t = 0; t < 4; ++t) {
                const int j = jb + t;
                if (j >= 3) {
                    if (j - 3 < NROW) pwS[n * JP + (j - 3)] = vj[t];
                } else {
                    dwS[n * 4 + j] = vj[t];
                }
            }
        }
    }
    __syncthreads();

    // ================= Phase B: depth = relu(depthwise conv over C) into s1 =================
    for (int idx = tid; idx < NROW * (CDIM / 4); idx += NTHR) {
        const int m = idx >> 6;
        const int c = (idx & 63) * 4;
        const float* vr = vg + m * CDIM;
        const float d0 = dwS[m * 4 + 0];
        const float d1 = dwS[m * 4 + 1];
        const float d2 = dwS[m * 4 + 2];
        const float4 vc = *(const float4*)(vr + c);
        const float vl  = (c == 0)        ? 0.0f : vr[c - 1];
        const float vrt = (c == CDIM - 4) ? 0.0f : vr[c + 4];
        float4 o;
        o.x = fmaxf(fmaf(d0, vl,   fmaf(d1, vc.x, d2 * vc.y)), 0.0f);
        o.y = fmaxf(fmaf(d0, vc.x, fmaf(d1, vc.y, d2 * vc.z)), 0.0f);
        o.z = fmaxf(fmaf(d0, vc.y, fmaf(d1, vc.z, d2 * vc.w)), 0.0f);
        o.w = fmaxf(fmaf(d0, vc.z, fmaf(d1, vc.w, d2 * vrt)), 0.0f);
        *(float4*)(s1 + m * CDIM + c) = o;
    }
    __syncthreads();

    // ================= Phase C: out = pw @ depth  (f32x2, conflict-free) =================
    // lane covers c = 4*lane (block 0) and c = 128 + 4*lane (block 1)
    const int cb0 = lane * 4;
    const int cb1 = 128 + lane * 4;
    u64 a2[RPW][4];
    #pragma unroll
    for (int r = 0; r < RPW; ++r)
        #pragma unroll
        for (int t = 0; t < 4; ++t) a2[r][t] = 0ull;

    #pragma unroll 1
    for (int m0 = 0; m0 < NROW; m0 += 4) {
        float4 pv[RPW];
        #pragma unroll
        for (int r = 0; r < RPW; ++r) {
            const int n = w + NWARP * r;
            if (n < NROW)
                pv[r] = *(const float4*)(pwS + n * JP + m0);   // aligned broadcast
        }
        #pragma unroll
        for (int mi = 0; mi < 4; ++mi) {
            const int m = m0 + mi;
            const ulonglong2 e0 = *(const ulonglong2*)(s1 + m * CDIM + cb0);
            const ulonglong2 e1 = *(const ulonglong2*)(s1 + m * CDIM + cb1);
            #pragma unroll
            for (int r = 0; r < RPW; ++r) {
                const int n = w + NWARP * r;
                if (n < NROW) {
                    const float ps = (mi == 0) ? pv[r].x : (mi == 1) ? pv[r].y
                                   : (mi == 2) ? pv[r].z : pv[r].w;
                    const u64 p2 = pack2(ps, ps);
                    fma2(a2[r][0], p2, e0.x);
                    fma2(a2[r][1], p2, e0.y);
                    fma2(a2[r][2], p2, e1.x);
                    fma2(a2[r][3], p2, e1.y);
                }
            }
        }
    }

    // ================= Phase D: LayerNorm over C + store =================
    const float rC = 1.0f / (float)CDIM;
    #pragma unroll
    for (int r = 0; r < RPW; ++r) {
        const int n = w + NWARP * r;
        if (n >= NROW) break;     // uniform across warp
        float2 v[4];
        #pragma unroll
        for (int t = 0; t < 4; ++t) v[t] = unpack2(a2[r][t]);
        float s = 0.0f, ss = 0.0f;
        #pragma unroll
        for (int t = 0; t < 4; ++t) {
            s += v[t].x + v[t].y;
            ss = fmaf(v[t].x, v[t].x, ss);
            ss = fmaf(v[t].y, v[t].y, ss);
        }
        #pragma unroll
        for (int o = 16; o > 0; o >>= 1) {
            s  += __shfl_xor_sync(0xffffffffu, s, o);
            ss += __shfl_xor_sync(0xffffffffu, ss, o);
        }
        const float mu  = s * rC;
        float var = fmaf(-mu, mu, ss * rC);
        var = fmaxf(var, 0.0f);
        const float inv = rsqrtf(var + 1e-5f);
        const float4 g0 = *(const float4*)(gamma + cb0);
        const float4 g1 = *(const float4*)(gamma + cb1);
        const float4 t0 = *(const float4*)(beta + cb0);
        const float4 t1 = *(const float4*)(beta + cb1);
        float4 o0, o1;
        o0.x = fmaf((v[0].x - mu) * inv, g0.x, t0.x);
        o0.y = fmaf((v[0].y - mu) * inv, g0.y, t0.y);
        o0.z = fmaf((v[1].x - mu) * inv, g0.z, t0.z);
        o0.w = fmaf((v[1].y - mu) * inv, g0.w, t0.w);
        o1.x = fmaf((v[2].x - mu) * inv, g1.x, t1.x);
        o1.y = fmaf((v[2].y - mu) * inv, g1.y, t1.y);
        o1.z = fmaf((v[3].x - mu) * inv, g1.z, t1.z);
        o1.w = fmaf((v[3].y - mu) * inv, g1.w, t1.w);
        *(float4*)(og + n * CDIM + cb0) = o0;
        *(float4*)(og + n * CDIM + cb1) = o1;
    }
}

extern "C" void kernel_launch(void* const* d_in, const int* in_sizes, int n_in,
                              void* d_out, int out_size)
{
    const float* query = (const float*)d_in[0];
    const float* value = (const float*)d_in[1];
    const float* Wwl   = (const float*)d_in[2];
    const float* bwl   = (const float*)d_in[3];
    const float* gamma = (const float*)d_in[4];
    const float* beta  = (const float*)d_in[5];
    float* out = (float*)d_out;

    const int B = in_sizes[0] / (NROW * CDIM);   // 512
    const size_t smem = SMEM_FLOATS * sizeof(float);   // 209,344 B
    cudaFuncSetAttribute(dysep_kernel,
                         cudaFuncAttributeMaxDynamicSharedMemorySize, (int)smem);
    dysep_kernel<<<B, NTHR, smem>>>(query, value, Wwl, bwl, gamma, beta, out);
}